// round 7
// baseline (speedup 1.0000x reference)
#include <cuda_runtime.h>
#include <cuda_bf16.h>
#include <math.h>

#define HW 65536
#define IMGW 256
#define DIMC 128
#define INNERC 512
#define OUTC 256
#define LEPS 1e-5f
#define ATT_SCALE 0.125f

// weight arena layout (u32 offsets)
#define OFF_Q     0
#define OFF_KV    32768
#define OFF_WO    98304
#define OFF_WIN   131072
#define OFF_WC1   139264
#define OFF_CONV  155648
#define LSTRIDE   303104
#define OFF_WOUT_H 606208
#define OFF_WOUT_L 614400
#define ARENA_SZ   622592

// ---------------- scratch (device globals; no allocation APIs) ----------------
__device__ float    g_x[DIMC * HW];
__device__ unsigned g_qkvp[768 * HW];
__device__ unsigned g_xph[256 * HW];
__device__ unsigned g_xpl[64 * HW];
__device__ unsigned g_warena[ARENA_SZ];

// ---------------- helpers ----------------
__device__ __forceinline__ unsigned pk2(float a, float b) {
    unsigned ua = (unsigned)__bfloat16_as_ushort(__float2bfloat16(a));
    unsigned ub = (unsigned)__bfloat16_as_ushort(__float2bfloat16(b));
    return ua | (ub << 16);
}
__device__ __forceinline__ float lof(float v) {
    return v - __bfloat162float(__float2bfloat16(v));
}
__device__ __forceinline__ float gelu_f(float v) {
    return 0.5f * v * (1.f + erff(v * 0.70710678118654752f));
}
__device__ __forceinline__ unsigned prmtf(unsigned a, unsigned b, unsigned s) {
    unsigned r;
    asm("prmt.b32 %0,%1,%2,%3;" : "=r"(r) : "r"(a), "r"(b), "r"(s));
    return r;
}

#define MMA16(c, a, b0, b1)                                                    \
    asm volatile(                                                              \
        "mma.sync.aligned.m16n8k16.row.col.f32.bf16.bf16.f32 "                 \
        "{%0,%1,%2,%3},{%4,%5,%6,%7},{%8,%9},{%0,%1,%2,%3};"                   \
        : "+f"((c)[0]), "+f"((c)[1]), "+f"((c)[2]), "+f"((c)[3])               \
        : "r"((a)[0]), "r"((a)[1]), "r"((a)[2]), "r"((a)[3]), "r"(b0), "r"(b1))

#define LDSM4(R, addr)                                                         \
    asm volatile("ldmatrix.sync.aligned.m8n8.x4.shared.b16 {%0,%1,%2,%3}, [%4];" \
        : "=r"((R)[0]), "=r"((R)[1]), "=r"((R)[2]), "=r"((R)[3])               \
        : "r"(addr))

__device__ __forceinline__ unsigned sm_addr(const void* p) {
    return (unsigned)__cvta_generic_to_shared(p);
}

// ---------------- all weight conversions in one kernel ----------------
__global__ void wconv_all(const float* __restrict__ wq, const float* __restrict__ wkv,
                          const float* __restrict__ wo, const float* __restrict__ w_in,
                          const float* __restrict__ w_c3, const float* __restrict__ w_c1,
                          const float* __restrict__ w_out, unsigned* __restrict__ ar) {
    int i = blockIdx.x * 256 + threadIdx.x;
    int s = blockIdx.y;
    if (s < 12) {
        int l = s / 6, t = s % 6;
        unsigned* dst = ar + (size_t)l * LSTRIDE;
        if (t == 0) {
            if (i < 32768) {
                float2 f = *(const float2*)&wq[(size_t)l * 65536 + 2 * i];
                dst[OFF_Q + i] = pk2(f.x * ATT_SCALE, f.y * ATT_SCALE);
            }
        } else if (t == 1) {
            if (i < 65536) {
                float2 f = *(const float2*)&wkv[(size_t)l * 131072 + 2 * i];
                dst[OFF_KV + i] = pk2(f.x, f.y);
            }
        } else if (t == 2) {
            if (i < 32768) {
                float2 f = *(const float2*)&wo[(size_t)l * 65536 + 2 * i];
                dst[OFF_WO + i] = pk2(f.x, f.y);
            }
        } else if (t == 3) {
            if (i < 8192) {
                float2 f = *(const float2*)&w_in[(size_t)l * 16384 + 2 * i];
                dst[OFF_WIN + i] = pk2(f.x, f.y);
            }
        } else if (t == 4) {
            if (i < 16384) {
                float2 f = *(const float2*)&w_c1[(size_t)l * 32768 + 2 * i];
                dst[OFF_WC1 + i] = pk2(f.x, f.y);
            }
        } else {
            if (i < 9 * OUTC * 64) {
                int tap = i / (OUTC * 64);
                int rem = i - tap * (OUTC * 64);
                int m = rem >> 6, kp = rem & 63;
                const float* w = w_c3 + (size_t)l * OUTC * DIMC * 9;
                float a = w[(size_t)m * (DIMC * 9) + (2 * kp) * 9 + tap];
                float b = w[(size_t)m * (DIMC * 9) + (2 * kp + 1) * 9 + tap];
                dst[OFF_CONV + i] = pk2(a, b);
            }
        }
    } else {
        if (i < 8192) {
            float2 f = *(const float2*)&w_out[2 * i];
            ar[OFF_WOUT_H + i] = pk2(f.x, f.y);
            ar[OFF_WOUT_L + i] = pk2(lof(f.x), lof(f.y));
        }
    }
}

__global__ void xcvt(const float* __restrict__ x, unsigned* __restrict__ yh,
                     unsigned* __restrict__ yl) {
    int i = blockIdx.x * 256 + threadIdx.x;
    int n = i & (HW - 1), kp = i >> 16;
    float v0 = x[(size_t)(2 * kp) * HW + n];
    float v1 = x[(size_t)(2 * kp + 1) * HW + n];
    yh[i] = pk2(v0, v1);
    yl[i] = pk2(lof(v0), lof(v1));
}

// ---------------- LayerNorm -> packed bf16 ----------------
__global__ void ln_kernel(const float* __restrict__ x, const float* __restrict__ g,
                          const float* __restrict__ b, unsigned* __restrict__ yh) {
    int p = blockIdx.x * blockDim.x + threadIdx.x;
    float s = 0.f, s2 = 0.f;
    #pragma unroll 8
    for (int c = 0; c < DIMC; c++) {
        float v = x[c * HW + p];
        s += v;
        s2 += v * v;
    }
    float mean = s * (1.f / DIMC);
    float var = fmaxf(s2 * (1.f / DIMC) - mean * mean, 0.f);
    float inv = 1.f / (sqrtf(var) + LEPS);
    #pragma unroll 4
    for (int cp = 0; cp < 64; cp++) {
        float v0 = (x[(2 * cp) * HW + p] - mean) * inv * g[2 * cp] + b[2 * cp];
        float v1 = (x[(2 * cp + 1) * HW + p] - mean) * inv * g[2 * cp + 1] + b[2 * cp + 1];
        yh[cp * HW + p] = pk2(v0, v1);
    }
}

// ---------------- bf16 GEMM: 128x128 CTA, 4 warps, 64x64 warp tiles ----------
__global__ __launch_bounds__(128) void gemm_bf16(
    const unsigned* __restrict__ W0, const unsigned* __restrict__ X0,
    const unsigned* __restrict__ W1, const unsigned* __restrict__ X1,
    const unsigned* __restrict__ W2, const unsigned* __restrict__ X2,
    int npass, const float* __restrict__ bias, const float* __restrict__ res,
    float* __restrict__ C, unsigned* __restrict__ Cp, int M, int K)
{
    __shared__ unsigned Xs[2][128 * 12];
    __shared__ unsigned Ws[2][128 * 12];
    int tid = threadIdx.x, lane = tid & 31, wid = tid >> 5;
    int n0 = blockIdx.x * 128, m0 = blockIdx.y * 128;
    int KP = K >> 1;
    int sps = K / 16, nsteps = npass * sps;
    int r = lane >> 2, q = lane & 3;
    int wpix = (wid >> 1) * 64, wch = (wid & 1) * 64;

    int arow = (lane & 7) | (((lane >> 3) & 1) << 3);
    int acol = (lane >> 4) & 1;
    int brow = ((lane >> 4) & 1) * 8 + (lane & 7);
    int bcol = (lane >> 3) & 1;
    unsigned baseX = sm_addr(&Xs[0][0]);
    unsigned baseW = sm_addr(&Ws[0][0]);
    unsigned aAddr[4], bAddr[4];
    #pragma unroll
    for (int ti = 0; ti < 4; ti++)
        aAddr[ti] = baseX + ((wpix + ti * 16 + arow) * 12 + acol * 4) * 4u;
    #pragma unroll
    for (int p = 0; p < 4; p++)
        bAddr[p] = baseW + ((wch + p * 16 + brow) * 12 + bcol * 4) * 4u;
    const unsigned BUF = 128 * 12 * 4;

    const unsigned* Wsel[3] = {W0, W1, W2};
    const unsigned* Xsel[3] = {X0, X1, X2};
    size_t wrow = (size_t)(m0 + tid) * KP;
    size_t xoff = (size_t)(n0 + tid);

    float acc[4][8][4];
    #pragma unroll
    for (int i = 0; i < 4; i++)
        #pragma unroll
        for (int j = 0; j < 8; j++)
            #pragma unroll
            for (int v = 0; v < 4; v++) acc[i][j][v] = 0.f;

    uint4 wv0, wv1;
    unsigned xr[8];
    {
        const unsigned* wp = W0 + wrow;
        wv0 = *(const uint4*)wp;
        wv1 = *(const uint4*)(wp + 4);
        const unsigned* xp = X0 + xoff;
        #pragma unroll
        for (int j = 0; j < 8; j++) xr[j] = xp[(size_t)j * HW];
        *(uint4*)&Ws[0][tid * 12] = wv0;
        *(uint4*)&Ws[0][tid * 12 + 4] = wv1;
        *(uint4*)&Xs[0][tid * 12] = make_uint4(xr[0], xr[1], xr[2], xr[3]);
        *(uint4*)&Xs[0][tid * 12 + 4] = make_uint4(xr[4], xr[5], xr[6], xr[7]);
    }
    __syncthreads();

    for (int s = 0; s < nsteps; s++) {
        int cur = s & 1;
        unsigned co = cur ? BUF : 0u;
        if (s + 1 < nsteps) {
            int s1 = s + 1;
            int seg = s1 / sps;
            int kp0 = (s1 - seg * sps) * 8;
            const unsigned* wp = Wsel[seg] + wrow + kp0;
            wv0 = *(const uint4*)wp;
            wv1 = *(const uint4*)(wp + 4);
            const unsigned* xp = Xsel[seg] + xoff + (size_t)kp0 * HW;
            #pragma unroll
            for (int j = 0; j < 8; j++) xr[j] = xp[(size_t)j * HW];
        }
        unsigned a[4][4];
        #pragma unroll
        for (int ti = 0; ti < 4; ti++) LDSM4(a[ti], aAddr[ti] + co);
        #pragma unroll
        for (int p = 0; p < 4; p++) {
            unsigned bb[4];
            LDSM4(bb, bAddr[p] + co);
            #pragma unroll
            for (int ti = 0; ti < 4; ti++) {
                MMA16(acc[ti][2 * p], a[ti], bb[0], bb[1]);
                MMA16(acc[ti][2 * p + 1], a[ti], bb[2], bb[3]);
            }
        }
        if (s + 1 < nsteps) {
            int nb = cur ^ 1;
            *(uint4*)&Ws[nb][tid * 12] = wv0;
            *(uint4*)&Ws[nb][tid * 12 + 4] = wv1;
            *(uint4*)&Xs[nb][tid * 12] = make_uint4(xr[0], xr[1], xr[2], xr[3]);
            *(uint4*)&Xs[nb][tid * 12 + 4] = make_uint4(xr[4], xr[5], xr[6], xr[7]);
            __syncthreads();
        }
    }

    #pragma unroll
    for (int ti = 0; ti < 4; ti++) {
        int pix = n0 + wpix + ti * 16 + r;
        #pragma unroll
        for (int tj = 0; tj < 8; tj++) {
            int ch0 = m0 + wch + tj * 8 + 2 * q;
            float b0v = bias ? bias[ch0] : 0.f;
            float b1v = bias ? bias[ch0 + 1] : 0.f;
            float v0 = acc[ti][tj][0] + b0v, v1 = acc[ti][tj][1] + b1v;
            float v2 = acc[ti][tj][2] + b0v, v3 = acc[ti][tj][3] + b1v;
            if (Cp) {
                int chp = ch0 >> 1;
                Cp[(size_t)chp * HW + pix] = pk2(v0, v1);
                Cp[(size_t)chp * HW + pix + 8] = pk2(v2, v3);
            } else {
                size_t i00 = (size_t)ch0 * HW + pix;
                size_t i10 = (size_t)(ch0 + 1) * HW + pix;
                if (res) {
                    v0 += res[i00]; v1 += res[i10];
                    v2 += res[i00 + 8]; v3 += res[i10 + 8];
                }
                C[i00] = v0; C[i10] = v1;
                C[i00 + 8] = v2; C[i10 + 8] = v3;
            }
        }
    }
}

// ---------------- window attention, packed bf16, ldmatrix frags ----------------
__global__ __launch_bounds__(256) void attn_kernel(const unsigned* __restrict__ qkv,
                                                   unsigned* __restrict__ outp) {
    __shared__ unsigned su[256 * 36];
    unsigned* Qs = su;
    unsigned* Ks = su;
    unsigned* Vs = su + 64 * 36;
    unsigned* Os = su;
    int blk = blockIdx.x;
    int wx = blk & 15, wy = (blk >> 4) & 15, h = blk >> 8;
    int tid = threadIdx.x, lane = tid & 31, wid = tid >> 5;
    int wbase = (wy << 12) | (wx << 4);
    int r = lane >> 2, q = lane & 3;
    const unsigned* Qg = qkv + (size_t)(h * 32) * HW;
    const unsigned* Kg = qkv + (size_t)(256 + h * 32) * HW;
    const unsigned* Vg = qkv + (size_t)(512 + h * 32) * HW;

    int arow = (lane & 7) | (((lane >> 3) & 1) << 3);
    int acol = (lane >> 4) & 1;
    int brow = ((lane >> 4) & 1) * 8 + (lane & 7);
    int bcol = (lane >> 3) & 1;
    unsigned baseS = sm_addr(&su[0]);

    for (int i = tid; i < 256 * 32; i += 256) {
        int n = i & 255, dp = i >> 8;
        int p = wbase + ((n >> 4) << 8) + (n & 15);
        Qs[n * 36 + dp] = Qg[(size_t)dp * HW + p];
    }
    __syncthreads();

    int wm = wid * 32;
    unsigned aQ[2][4][4];
    #pragma unroll
    for (int ti = 0; ti < 2; ti++) {
        unsigned ab = baseS + ((wm + ti * 16 + arow) * 36 + acol * 4) * 4u;
        #pragma unroll
        for (int kk = 0; kk < 4; kk++)
            LDSM4(aQ[ti][kk], ab + kk * 32u);
    }
    __syncthreads();

    unsigned kAddr[4], vAddr[4];
    #pragma unroll
    for (int p = 0; p < 4; p++) {
        kAddr[p] = baseS + ((p * 16 + brow) * 36 + bcol * 4) * 4u;
        vAddr[p] = baseS + (64 * 36 + (p * 16 + brow) * 36 + bcol * 4) * 4u;
    }

    float o[2][8][4];
    #pragma unroll
    for (int i = 0; i < 2; i++)
        #pragma unroll
        for (int j = 0; j < 8; j++)
            #pragma unroll
            for (int v = 0; v < 4; v++) o[i][j][v] = 0.f;
    float rs[2][2] = {{0.f, 0.f}, {0.f, 0.f}};

    for (int jc = 0; jc < 256; jc += 64) {
        for (int i = tid; i < 64 * 32; i += 256) {
            int jl = i & 63, dp = i >> 6;
            int j = jc + jl;
            int pj = wbase + ((j >> 4) << 8) + (j & 15);
            Ks[jl * 36 + dp] = Kg[(size_t)dp * HW + pj];
        }
        for (int i = tid; i < 32 * 32; i += 256) {
            int dp = i >> 5, jp = i & 31;
            int j0 = jc + 2 * jp;
            int pj = wbase + ((j0 >> 4) << 8) + (j0 & 15);
            uint2 vv = *(const uint2*)&Vg[(size_t)dp * HW + pj];
            Vs[(2 * dp) * 36 + jp] = prmtf(vv.x, vv.y, 0x5410u);
            Vs[(2 * dp + 1) * 36 + jp] = prmtf(vv.x, vv.y, 0x7632u);
        }
        __syncthreads();

        #pragma unroll
        for (int ti = 0; ti < 2; ti++) {
            float e[8][4];
            #pragma unroll
            for (int tjp = 0; tjp < 4; tjp++) {
                float c0[4] = {0.f, 0.f, 0.f, 0.f};
                float c1[4] = {0.f, 0.f, 0.f, 0.f};
                #pragma unroll
                for (int kk = 0; kk < 4; kk++) {
                    unsigned bb[4];
                    LDSM4(bb, kAddr[tjp] + kk * 32u);
                    MMA16(c0, aQ[ti][kk], bb[0], bb[1]);
                    MMA16(c1, aQ[ti][kk], bb[2], bb[3]);
                }
                #pragma unroll
                for (int v = 0; v < 4; v++) {
                    e[2 * tjp][v] = __expf(c0[v]);
                    e[2 * tjp + 1][v] = __expf(c1[v]);
                }
                rs[ti][0] += e[2 * tjp][0] + e[2 * tjp][1] +
                             e[2 * tjp + 1][0] + e[2 * tjp + 1][1];
                rs[ti][1] += e[2 * tjp][2] + e[2 * tjp][3] +
                             e[2 * tjp + 1][2] + e[2 * tjp + 1][3];
            }
            #pragma unroll
            for (int kk2 = 0; kk2 < 4; kk2++) {
                unsigned aP[4];
                aP[0] = pk2(e[2 * kk2][0], e[2 * kk2][1]);
                aP[1] = pk2(e[2 * kk2][2], e[2 * kk2][3]);
                aP[2] = pk2(e[2 * kk2 + 1][0], e[2 * kk2 + 1][1]);
                aP[3] = pk2(e[2 * kk2 + 1][2], e[2 * kk2 + 1][3]);
                #pragma unroll
                for (int tdjp = 0; tdjp < 4; tdjp++) {
                    unsigned bv[4];
                    LDSM4(bv, vAddr[tdjp] + kk2 * 32u);
                    MMA16(o[ti][2 * tdjp], aP, bv[0], bv[1]);
                    MMA16(o[ti][2 * tdjp + 1], aP, bv[2], bv[3]);
                }
            }
        }
        __syncthreads();
    }

    #pragma unroll
    for (int ti = 0; ti < 2; ti++) {
        #pragma unroll
        for (int hh = 0; hh < 2; hh++) {
            rs[ti][hh] += __shfl_xor_sync(0xffffffffu, rs[ti][hh], 1);
            rs[ti][hh] += __shfl_xor_sync(0xffffffffu, rs[ti][hh], 2);
        }
    }

    #pragma unroll
    for (int ti = 0; ti < 2; ti++) {
        int t0 = wm + ti * 16 + r;
        float i0 = 1.f / rs[ti][0], i1 = 1.f / rs[ti][1];
        #pragma unroll
        for (int tdj = 0; tdj < 8; tdj++) {
            int kpl = tdj * 4 + q;
            Os[kpl * 260 + t0] = pk2(o[ti][tdj][0] * i0, o[ti][tdj][1] * i0);
            Os[kpl * 260 + t0 + 8] = pk2(o[ti][tdj][2] * i1, o[ti][tdj][3] * i1);
        }
    }
    __syncthreads();
    for (int i = tid; i < 32 * 256; i += 256) {
        int kpl = i >> 8, n = i & 255;
        int p = wbase + ((n >> 4) << 8) + (n & 15);
        outp[(size_t)(h * 32 + kpl) * HW + p] = Os[kpl * 260 + n];
    }
}

// ---------------- 3x3 conv implicit GEMM + bias + GELU ----------------
__global__ __launch_bounds__(256, 2) void conv3_kernel(
    const unsigned* __restrict__ Wp, const unsigned* __restrict__ Xp,
    const float* __restrict__ bias, unsigned* __restrict__ Cp)
{
    extern __shared__ unsigned cs[];
    unsigned* Wsm = cs;              // [128 ch][68]
    unsigned* Xsm = cs + 128 * 68;   // [130 px][68]
    int tid = threadIdx.x, lane = tid & 31, wid = tid >> 5;
    int n0 = blockIdx.x * 128;
    int m0 = blockIdx.y * 128;
    int y0 = n0 >> 8, x0 = n0 & 255;
    int r = lane >> 2, q = lane & 3;
    int wpix = (wid & 3) * 32, wch = (wid >> 2) * 64;

    int arow = (lane & 7) | (((lane >> 3) & 1) << 3);
    int acol = (lane >> 4) & 1;
    int brow = ((lane >> 4) & 1) * 8 + (lane & 7);
    int bcol = (lane >> 3) & 1;
    unsigned baseW = sm_addr(&Wsm[0]);
    unsigned baseX = sm_addr(&Xsm[0]);
    unsigned bAddr[4];
    #pragma unroll
    for (int p = 0; p < 4; p++)
        bAddr[p] = baseW + ((wch + p * 16 + brow) * 68 + bcol * 4) * 4u;

    float acc[2][8][4];
    #pragma unroll
    for (int i = 0; i < 2; i++)
        #pragma unroll
        for (int j = 0; j < 8; j++)
            #pragma unroll
            for (int v = 0; v < 4; v++) acc[i][j][v] = 0.f;

    for (int dy = 0; dy < 3; dy++) {
        int ys = y0 + dy - 1;
        bool yok = (ys >= 0) && (ys < IMGW);
        __syncthreads();
        for (int i = tid; i < 130 * 64; i += 256) {
            int px = i % 130, kp = i / 130;
            int xs = x0 - 1 + px;
            unsigned v = 0u;
            if (yok && xs >= 0 && xs < IMGW)
                v = Xp[(size_t)kp * HW + (ys << 8) + xs];
            Xsm[px * 68 + kp] = v;
        }
        for (int dx = 0; dx < 3; dx++) {
            int tap = dy * 3 + dx;
            __syncthreads();
            for (int i = tid; i < 128 * 16; i += 256) {
                int ch = i >> 4, k4 = (i & 15) << 2;
                *(uint4*)&Wsm[ch * 68 + k4] =
                    *(const uint4*)&Wp[(size_t)tap * (OUTC * 64) +
                                       (size_t)(m0 + ch) * 64 + k4];
            }
            __syncthreads();
            unsigned aA0 = baseX + ((wpix + dx + arow) * 68 + acol * 4) * 4u;
            unsigned aA1 = baseX + ((wpix + 16 + dx + arow) * 68 + acol * 4) * 4u;
            #pragma unroll
            for (int kk = 0; kk < 8; kk++) {
                unsigned a0[4], a1[4];
                LDSM4(a0, aA0 + kk * 32u);
                LDSM4(a1, aA1 + kk * 32u);
                #pragma unroll
                for (int p = 0; p < 4; p++) {
                    unsigned bb[4];
                    LDSM4(bb, bAddr[p] + kk * 32u);
                    MMA16(acc[0][2 * p], a0, bb[0], bb[1]);
                    MMA16(acc[1][2 * p], a1, bb[0], bb[1]);
                    MMA16(acc[0][2 * p + 1], a0, bb[2], bb[3]);
                    MMA16(acc[1][2 * p + 1], a1, bb[2], bb[3]);
                }
            }
        }
    }

    #pragma unroll
    for (int ti = 0; ti < 2; ti++) {
        int pix = n0 + wpix + ti * 16 + r;
        #pragma unroll
        for (int tj = 0; tj < 8; tj++) {
            int ch0 = m0 + wch + tj * 8 + 2 * q;
            int chp = ch0 >> 1;
            float b0v = bias[ch0], b1v = bias[ch0 + 1];
            float v0 = gelu_f(acc[ti][tj][0] + b0v);
            float v1 = gelu_f(acc[ti][tj][1] + b1v);
            float v2 = gelu_f(acc[ti][tj][2] + b0v);
            float v3 = gelu_f(acc[ti][tj][3] + b1v);
            Cp[(size_t)chp * HW + pix] = pk2(v0, v1);
            Cp[(size_t)chp * HW + pix + 8] = pk2(v2, v3);
        }
    }
}

// ---------------- host orchestration ----------------
extern "C" void kernel_launch(void* const* d_in, const int* in_sizes, int n_in,
                              void* d_out, int out_size) {
    const float* x     = (const float*)d_in[0];
    const float* ln1_g = (const float*)d_in[1];
    const float* ln1_b = (const float*)d_in[2];
    const float* wq    = (const float*)d_in[3];
    const float* wkv   = (const float*)d_in[4];
    const float* wo    = (const float*)d_in[5];
    const float* bo    = (const float*)d_in[6];
    const float* ln2_g = (const float*)d_in[7];
    const float* ln2_b = (const float*)d_in[8];
    const float* w_in  = (const float*)d_in[9];
    const float* b_in  = (const float*)d_in[10];
    const float* w_c3  = (const float*)d_in[11];
    const float* b_c3  = (const float*)d_in[12];
    const float* w_c1  = (const float*)d_in[13];
    const float* b_c1  = (const float*)d_in[14];
    const float* w_out = (const float*)d_in[15];
    const float* b_out = (const float*)d_in[16];
    float* out = (float*)d_out;

    float* px;
    unsigned *pqkv, *pxh, *pxl, *par;
    cudaGetSymbolAddress((void**)&px,   g_x);
    cudaGetSymbolAddress((void**)&pqkv, g_qkvp);
    cudaGetSymbolAddress((void**)&pxh,  g_xph);
    cudaGetSymbolAddress((void**)&pxl,  g_xpl);
    cudaGetSymbolAddress((void**)&par,  g_warena);

    cudaFuncSetAttribute(conv3_kernel,
                         cudaFuncAttributeMaxDynamicSharedMemorySize, 70176);

    cudaMemcpyAsync(px, x, (size_t)DIMC * HW * sizeof(float),
                    cudaMemcpyDeviceToDevice);
    wconv_all<<<dim3(576, 13), 256>>>(wq, wkv, wo, w_in, w_c3, w_c1, w_out, par);

    for (int l = 0; l < 2; l++) {
        unsigned* wb = par + (size_t)l * LSTRIDE;
        ln_kernel<<<HW / 256, 256>>>(px, ln1_g + l * DIMC, ln1_b + l * DIMC, pxh);
        // merged q+kv GEMM: M = 1536 (wq | wkv contiguous in arena)
        gemm_bf16<<<dim3(512, 12), 128>>>(wb + OFF_Q, pxh, wb, pxh, wb, pxh, 1,
                                          nullptr, nullptr, nullptr, pqkv,
                                          3 * INNERC, DIMC);
        attn_kernel<<<2048, 256>>>(pqkv, pxh);
        gemm_bf16<<<dim3(512, 1), 128>>>(wb + OFF_WO, pxh, wb, pxh, wb, pxh, 1,
                                         bo + l * DIMC, px, px, nullptr,
                                         DIMC, INNERC);
        ln_kernel<<<HW / 256, 256>>>(px, ln2_g + l * DIMC, ln2_b + l * DIMC, pxh);
        gemm_bf16<<<dim3(512, 1), 128>>>(wb + OFF_WIN, pxh, wb, pxh, wb, pxh, 1,
                                         b_in + l * DIMC, nullptr, nullptr,
                                         pqkv, DIMC, DIMC);
        conv3_kernel<<<dim3(512, 2), 256, 70176>>>(wb + OFF_CONV, pqkv,
                                                   b_c3 + l * OUTC, pxh);
        gemm_bf16<<<dim3(512, 1), 128>>>(wb + OFF_WC1, pxh, wb, pxh, wb, pxh, 1,
                                         b_c1 + l * DIMC, px, px, nullptr,
                                         DIMC, OUTC);
    }
    xcvt<<<64 * HW / 256, 256>>>(px, pxh, pxl);
    gemm_bf16<<<dim3(512, 1), 128>>>(par + OFF_WOUT_H, pxh,
                                     par + OFF_WOUT_H, pxl,
                                     par + OFF_WOUT_L, pxh, 3,
                                     b_out, px, out, nullptr, DIMC, DIMC);
}

// round 12
// speedup vs baseline: 1.2937x; 1.2937x over previous
#include <cuda_runtime.h>
#include <cuda_bf16.h>
#include <math.h>

#define HW 65536
#define IMGW 256
#define DIMC 128
#define INNERC 512
#define OUTC 256
#define LEPS 1e-5f
#define ATT_SCALE 0.125f
#define LOG2E 1.4426950408889634f

// weight arena layout (u32 offsets)
#define OFF_Q     0
#define OFF_KV    32768
#define OFF_WO    98304
#define OFF_WIN   131072
#define OFF_WC1   139264
#define OFF_CONV  155648
#define LSTRIDE   303104
#define OFF_WOUT_H 606208
#define OFF_WOUT_L 614400
#define ARENA_SZ   622592

// ---------------- scratch (device globals; no allocation APIs) ----------------
__device__ float    g_x[DIMC * HW];
__device__ unsigned g_qkvp[768 * HW];
__device__ unsigned g_xph[256 * HW];
__device__ unsigned g_xpl[64 * HW];
__device__ unsigned g_warena[ARENA_SZ];

// ---------------- helpers ----------------
__device__ __forceinline__ unsigned pk2(float lo, float hi) {
    unsigned r;
    asm("cvt.rn.bf16x2.f32 %0, %1, %2;" : "=r"(r) : "f"(hi), "f"(lo));
    return r;
}
__device__ __forceinline__ float lof(float v) {
    return v - __bfloat162float(__float2bfloat16(v));
}
__device__ __forceinline__ float gelu_f(float v) {
    return 0.5f * v * (1.f + erff(v * 0.70710678118654752f));
}
__device__ __forceinline__ float ex2f(float v) {
    float r;
    asm("ex2.approx.f32 %0, %1;" : "=f"(r) : "f"(v));
    return r;
}
__device__ __forceinline__ unsigned prmtf(unsigned a, unsigned b, unsigned s) {
    unsigned r;
    asm("prmt.b32 %0,%1,%2,%3;" : "=r"(r) : "r"(a), "r"(b), "r"(s));
    return r;
}

#define MMA16(c, a, b0, b1)                                                    \
    asm volatile(                                                              \
        "mma.sync.aligned.m16n8k16.row.col.f32.bf16.bf16.f32 "                 \
        "{%0,%1,%2,%3},{%4,%5,%6,%7},{%8,%9},{%0,%1,%2,%3};"                   \
        : "+f"((c)[0]), "+f"((c)[1]), "+f"((c)[2]), "+f"((c)[3])               \
        : "r"((a)[0]), "r"((a)[1]), "r"((a)[2]), "r"((a)[3]), "r"(b0), "r"(b1))

#define LDSM4(R, addr)                                                         \
    asm volatile("ldmatrix.sync.aligned.m8n8.x4.shared.b16 {%0,%1,%2,%3}, [%4];" \
        : "=r"((R)[0]), "=r"((R)[1]), "=r"((R)[2]), "=r"((R)[3])               \
        : "r"(addr))

__device__ __forceinline__ unsigned sm_addr(const void* p) {
    return (unsigned)__cvta_generic_to_shared(p);
}

// ---------------- all weight conversions in one kernel ----------------
__global__ void wconv_all(const float* __restrict__ wq, const float* __restrict__ wkv,
                          const float* __restrict__ wo, const float* __restrict__ w_in,
                          const float* __restrict__ w_c3, const float* __restrict__ w_c1,
                          const float* __restrict__ w_out, unsigned* __restrict__ ar) {
    int i = blockIdx.x * 256 + threadIdx.x;
    int s = blockIdx.y;
    if (s < 12) {
        int l = s / 6, t = s % 6;
        unsigned* dst = ar + (size_t)l * LSTRIDE;
        if (t == 0) {
            if (i < 32768) {
                float2 f = *(const float2*)&wq[(size_t)l * 65536 + 2 * i];
                float sc = ATT_SCALE * LOG2E;   // fold softmax scale + log2e
                dst[OFF_Q + i] = pk2(f.x * sc, f.y * sc);
            }
        } else if (t == 1) {
            if (i < 65536) {
                float2 f = *(const float2*)&wkv[(size_t)l * 131072 + 2 * i];
                dst[OFF_KV + i] = pk2(f.x, f.y);
            }
        } else if (t == 2) {
            if (i < 32768) {
                float2 f = *(const float2*)&wo[(size_t)l * 65536 + 2 * i];
                dst[OFF_WO + i] = pk2(f.x, f.y);
            }
        } else if (t == 3) {
            if (i < 8192) {
                float2 f = *(const float2*)&w_in[(size_t)l * 16384 + 2 * i];
                dst[OFF_WIN + i] = pk2(f.x, f.y);
            }
        } else if (t == 4) {
            if (i < 16384) {
                float2 f = *(const float2*)&w_c1[(size_t)l * 32768 + 2 * i];
                dst[OFF_WC1 + i] = pk2(f.x, f.y);
            }
        } else {
            if (i < 9 * OUTC * 64) {
                int tap = i / (OUTC * 64);
                int rem = i - tap * (OUTC * 64);
                int m = rem >> 6, kp = rem & 63;
                const float* w = w_c3 + (size_t)l * OUTC * DIMC * 9;
                float a = w[(size_t)m * (DIMC * 9) + (2 * kp) * 9 + tap];
                float b = w[(size_t)m * (DIMC * 9) + (2 * kp + 1) * 9 + tap];
                dst[OFF_CONV + i] = pk2(a, b);
            }
        }
    } else {
        if (i < 8192) {
            float2 f = *(const float2*)&w_out[2 * i];
            ar[OFF_WOUT_H + i] = pk2(f.x, f.y);
            ar[OFF_WOUT_L + i] = pk2(lof(f.x), lof(f.y));
        }
    }
}

__global__ void xcvt(const float* __restrict__ x, unsigned* __restrict__ yh,
                     unsigned* __restrict__ yl) {
    int i = blockIdx.x * 256 + threadIdx.x;
    int n = i & (HW - 1), kp = i >> 16;
    float v0 = x[(size_t)(2 * kp) * HW + n];
    float v1 = x[(size_t)(2 * kp + 1) * HW + n];
    yh[i] = pk2(v0, v1);
    yl[i] = pk2(lof(v0), lof(v1));
}

// ---------------- LayerNorm -> packed bf16 ----------------
__global__ void ln_kernel(const float* __restrict__ x, const float* __restrict__ g,
                          const float* __restrict__ b, unsigned* __restrict__ yh) {
    int p = blockIdx.x * blockDim.x + threadIdx.x;
    float s = 0.f, s2 = 0.f;
    #pragma unroll 8
    for (int c = 0; c < DIMC; c++) {
        float v = x[c * HW + p];
        s += v;
        s2 += v * v;
    }
    float mean = s * (1.f / DIMC);
    float var = fmaxf(s2 * (1.f / DIMC) - mean * mean, 0.f);
    float inv = 1.f / (sqrtf(var) + LEPS);
    #pragma unroll 4
    for (int cp = 0; cp < 64; cp++) {
        float v0 = (x[(2 * cp) * HW + p] - mean) * inv * g[2 * cp] + b[2 * cp];
        float v1 = (x[(2 * cp + 1) * HW + p] - mean) * inv * g[2 * cp + 1] + b[2 * cp + 1];
        yh[cp * HW + p] = pk2(v0, v1);
    }
}

// ---------------- bf16 GEMM (R5 config: 256 thr, 32x64 warp tiles) ----------
__global__ __launch_bounds__(256) void gemm_bf16(
    const unsigned* __restrict__ W0, const unsigned* __restrict__ X0,
    const unsigned* __restrict__ W1, const unsigned* __restrict__ X1,
    const unsigned* __restrict__ W2, const unsigned* __restrict__ X2,
    int npass, const float* __restrict__ bias, const float* __restrict__ res,
    float* __restrict__ C, unsigned* __restrict__ Cp, int M, int K)
{
    __shared__ unsigned Xs[2][128 * 12];
    __shared__ unsigned Ws[2][128 * 12];
    int tid = threadIdx.x, lane = tid & 31, wid = tid >> 5;
    int n0 = blockIdx.x * 128, m0 = blockIdx.y * 128;
    int KP = K >> 1;
    int sps = K / 16, nsteps = npass * sps;
    int r = lane >> 2, q = lane & 3;
    int wpix = (wid & 3) * 32, wch = (wid >> 2) * 64;
    int xn = tid & 127, xk = (tid >> 7) * 4;
    int wm = tid >> 1, wk = (tid & 1) * 4;

    int arow = (lane & 7) | (((lane >> 3) & 1) << 3);
    int acol = (lane >> 4) & 1;
    int brow = ((lane >> 4) & 1) * 8 + (lane & 7);
    int bcol = (lane >> 3) & 1;
    unsigned baseX = sm_addr(&Xs[0][0]);
    unsigned baseW = sm_addr(&Ws[0][0]);
    unsigned aAddr[2], bAddr[4];
    #pragma unroll
    for (int ti = 0; ti < 2; ti++)
        aAddr[ti] = baseX + ((wpix + ti * 16 + arow) * 12 + acol * 4) * 4u;
    #pragma unroll
    for (int p = 0; p < 4; p++)
        bAddr[p] = baseW + ((wch + p * 16 + brow) * 12 + bcol * 4) * 4u;
    const unsigned BUF = 128 * 12 * 4;

    const unsigned* Wsel[3] = {W0, W1, W2};
    const unsigned* Xsel[3] = {X0, X1, X2};

    float acc[2][8][4];
    #pragma unroll
    for (int i = 0; i < 2; i++)
        #pragma unroll
        for (int j = 0; j < 8; j++)
            #pragma unroll
            for (int v = 0; v < 4; v++) acc[i][j][v] = 0.f;

    unsigned wr[4], xr[4];
    #pragma unroll
    for (int j = 0; j < 4; j++) {
        wr[j] = W0[(size_t)(m0 + wm) * KP + wk + j];
        xr[j] = X0[(size_t)(xk + j) * HW + n0 + xn];
    }
    #pragma unroll
    for (int j = 0; j < 4; j++) {
        Ws[0][wm * 12 + wk + j] = wr[j];
        Xs[0][xn * 12 + xk + j] = xr[j];
    }
    __syncthreads();

    for (int s = 0; s < nsteps; s++) {
        int cur = s & 1;
        unsigned co = cur ? BUF : 0u;
        if (s + 1 < nsteps) {
            int s1 = s + 1;
            int seg = s1 / sps;
            int kp0 = (s1 - seg * sps) * 8;
            const unsigned* Wg = Wsel[seg];
            const unsigned* Xg = Xsel[seg];
            #pragma unroll
            for (int j = 0; j < 4; j++) {
                wr[j] = Wg[(size_t)(m0 + wm) * KP + kp0 + wk + j];
                xr[j] = Xg[(size_t)(kp0 + xk + j) * HW + n0 + xn];
            }
        }
        unsigned a0[4], a1[4];
        LDSM4(a0, aAddr[0] + co);
        LDSM4(a1, aAddr[1] + co);
        #pragma unroll
        for (int p = 0; p < 4; p++) {
            unsigned bb[4];
            LDSM4(bb, bAddr[p] + co);
            MMA16(acc[0][2 * p], a0, bb[0], bb[1]);
            MMA16(acc[1][2 * p], a1, bb[0], bb[1]);
            MMA16(acc[0][2 * p + 1], a0, bb[2], bb[3]);
            MMA16(acc[1][2 * p + 1], a1, bb[2], bb[3]);
        }
        if (s + 1 < nsteps) {
            int nb = cur ^ 1;
            #pragma unroll
            for (int j = 0; j < 4; j++) {
                Ws[nb][wm * 12 + wk + j] = wr[j];
                Xs[nb][xn * 12 + xk + j] = xr[j];
            }
            __syncthreads();
        }
    }

    #pragma unroll
    for (int ti = 0; ti < 2; ti++) {
        int pix = n0 + wpix + ti * 16 + r;
        #pragma unroll
        for (int tj = 0; tj < 8; tj++) {
            int ch0 = m0 + wch + tj * 8 + 2 * q;
            float b0v = bias ? bias[ch0] : 0.f;
            float b1v = bias ? bias[ch0 + 1] : 0.f;
            float v0 = acc[ti][tj][0] + b0v, v1 = acc[ti][tj][1] + b1v;
            float v2 = acc[ti][tj][2] + b0v, v3 = acc[ti][tj][3] + b1v;
            if (Cp) {
                int chp = ch0 >> 1;
                Cp[(size_t)chp * HW + pix] = pk2(v0, v1);
                Cp[(size_t)chp * HW + pix + 8] = pk2(v2, v3);
            } else {
                size_t i00 = (size_t)ch0 * HW + pix;
                size_t i10 = (size_t)(ch0 + 1) * HW + pix;
                if (res) {
                    v0 += res[i00]; v1 += res[i10];
                    v2 += res[i00 + 8]; v3 += res[i10 + 8];
                }
                C[i00] = v0; C[i10] = v1;
                C[i00 + 8] = v2; C[i10 + 8] = v3;
            }
        }
    }
}

// ---------------- window attention: fused S->P->PV, 128-token chunks ----------
// smem (dynamic 72704B): Qs [256][36] | Ks [128][36] | Vs [64][68]; Os overlays Qs.
__global__ __launch_bounds__(256, 2) void attn_kernel(const unsigned* __restrict__ qkv,
                                                      unsigned* __restrict__ outp) {
    extern __shared__ unsigned su[];
    unsigned* Qs = su;
    unsigned* Ks = su + 9216;
    unsigned* Vs = su + 13824;
    unsigned* Os = su;
    int blk = blockIdx.x;
    int wx = blk & 15, wy = (blk >> 4) & 15, h = blk >> 8;
    int tid = threadIdx.x, lane = tid & 31, wid = tid >> 5;
    int wbase = (wy << 12) | (wx << 4);
    int r = lane >> 2, q = lane & 3;
    const unsigned* Qg = qkv + (size_t)(h * 32) * HW;
    const unsigned* Kg = qkv + (size_t)(256 + h * 32) * HW;
    const unsigned* Vg = qkv + (size_t)(512 + h * 32) * HW;

    int arow = (lane & 7) | (((lane >> 3) & 1) << 3);
    int acol = (lane >> 4) & 1;
    int brow = ((lane >> 4) & 1) * 8 + (lane & 7);
    int bcol = (lane >> 3) & 1;
    unsigned baseS = sm_addr(&su[0]);
    int wm = wid * 32;

    // stage Q -> smem
    for (int i = tid; i < 256 * 32; i += 256) {
        int n = i & 255, dp = i >> 8;
        int p = wbase + ((n >> 4) << 8) + (n & 15);
        Qs[n * 36 + dp] = Qg[(size_t)dp * HW + p];
    }
    __syncthreads();

    // preload Q fragments (both 16-row tiles, all 4 k-groups)
    unsigned aQ[2][4][4];
    #pragma unroll
    for (int ti = 0; ti < 2; ti++) {
        unsigned ab = baseS + ((wm + ti * 16 + arow) * 36 + acol * 4) * 4u;
        #pragma unroll
        for (int kk = 0; kk < 4; kk++)
            LDSM4(aQ[ti][kk], ab + kk * 32u);
    }

    unsigned kb = baseS + 9216u * 4u + ((unsigned)(brow * 36 + bcol * 4)) * 4u;
    unsigned vb = baseS + 13824u * 4u + ((unsigned)(brow * 68 + bcol * 4)) * 4u;

    float o[2][8][4];
    #pragma unroll
    for (int i = 0; i < 2; i++)
        #pragma unroll
        for (int j = 0; j < 8; j++)
            #pragma unroll
            for (int v = 0; v < 4; v++) o[i][j][v] = 0.f;
    float rs[2][2] = {{0.f, 0.f}, {0.f, 0.f}};

    for (int jc = 0; jc < 256; jc += 128) {
        __syncthreads();   // prev chunk compute done before K/V overwrite
        for (int i = tid; i < 128 * 32; i += 256) {
            int jl = i & 127, dp = i >> 7;
            int j = jc + jl;
            int pj = wbase + ((j >> 4) << 8) + (j & 15);
            Ks[jl * 36 + dp] = Kg[(size_t)dp * HW + pj];
        }
        for (int i = tid; i < 32 * 64; i += 256) {
            int dp = i >> 6, jp = i & 63;
            int j0 = jc + 2 * jp;
            int pj = wbase + ((j0 >> 4) << 8) + (j0 & 15);
            uint2 vv = *(const uint2*)&Vg[(size_t)dp * HW + pj];
            Vs[(2 * dp) * 68 + jp] = prmtf(vv.x, vv.y, 0x5410u);
            Vs[(2 * dp + 1) * 68 + jp] = prmtf(vv.x, vv.y, 0x7632u);
        }
        __syncthreads();

        #pragma unroll
        for (int tjp = 0; tjp < 8; tjp++) {
            float c[2][2][4];
            #pragma unroll
            for (int ti = 0; ti < 2; ti++)
                #pragma unroll
                for (int hh = 0; hh < 2; hh++)
                    #pragma unroll
                    for (int v = 0; v < 4; v++) c[ti][hh][v] = 0.f;
            #pragma unroll
            for (int kk = 0; kk < 4; kk++) {
                unsigned bb[4];
                LDSM4(bb, kb + tjp * 2304u + kk * 32u);
                MMA16(c[0][0], aQ[0][kk], bb[0], bb[1]);
                MMA16(c[0][1], aQ[0][kk], bb[2], bb[3]);
                MMA16(c[1][0], aQ[1][kk], bb[0], bb[1]);
                MMA16(c[1][1], aQ[1][kk], bb[2], bb[3]);
            }
            unsigned aP[2][4];
            #pragma unroll
            for (int ti = 0; ti < 2; ti++) {
                float e00 = ex2f(c[ti][0][0]), e01 = ex2f(c[ti][0][1]);
                float e02 = ex2f(c[ti][0][2]), e03 = ex2f(c[ti][0][3]);
                float e10 = ex2f(c[ti][1][0]), e11 = ex2f(c[ti][1][1]);
                float e12 = ex2f(c[ti][1][2]), e13 = ex2f(c[ti][1][3]);
                rs[ti][0] += e00 + e01 + e10 + e11;
                rs[ti][1] += e02 + e03 + e12 + e13;
                aP[ti][0] = pk2(e00, e01);
                aP[ti][1] = pk2(e02, e03);
                aP[ti][2] = pk2(e10, e11);
                aP[ti][3] = pk2(e12, e13);
            }
            #pragma unroll
            for (int tdjp = 0; tdjp < 4; tdjp++) {
                unsigned bv[4];
                LDSM4(bv, vb + tdjp * 4352u + tjp * 32u);
                MMA16(o[0][2 * tdjp], aP[0], bv[0], bv[1]);
                MMA16(o[0][2 * tdjp + 1], aP[0], bv[2], bv[3]);
                MMA16(o[1][2 * tdjp], aP[1], bv[0], bv[1]);
                MMA16(o[1][2 * tdjp + 1], aP[1], bv[2], bv[3]);
            }
        }
    }

    #pragma unroll
    for (int ti = 0; ti < 2; ti++) {
        #pragma unroll
        for (int hh = 0; hh < 2; hh++) {
            rs[ti][hh] += __shfl_xor_sync(0xffffffffu, rs[ti][hh], 1);
            rs[ti][hh] += __shfl_xor_sync(0xffffffffu, rs[ti][hh], 2);
        }
    }

    __syncthreads();   // all K/V consumption done; Os overlays Qs
    #pragma unroll
    for (int ti = 0; ti < 2; ti++) {
        int t0 = wm + ti * 16 + r;
        float i0 = 1.f / rs[ti][0], i1 = 1.f / rs[ti][1];
        #pragma unroll
        for (int tdj = 0; tdj < 8; tdj++) {
            int kpl = tdj * 4 + q;
            Os[kpl * 260 + t0] = pk2(o[ti][tdj][0] * i0, o[ti][tdj][1] * i0);
            Os[kpl * 260 + t0 + 8] = pk2(o[ti][tdj][2] * i1, o[ti][tdj][3] * i1);
        }
    }
    __syncthreads();
    for (int i = tid; i < 32 * 256; i += 256) {
        int kpl = i >> 8, n = i & 255;
        int p = wbase + ((n >> 4) << 8) + (n & 15);
        outp[(size_t)(h * 32 + kpl) * HW + p] = Os[kpl * 260 + n];
    }
}

// ---------------- 3x3 conv implicit GEMM + bias + GELU ----------------
__global__ __launch_bounds__(256, 2) void conv3_kernel(
    const unsigned* __restrict__ Wp, const unsigned* __restrict__ Xp,
    const float* __restrict__ bias, unsigned* __restrict__ Cp)
{
    extern __shared__ unsigned cs[];
    unsigned* Wsm = cs;              // [128 ch][68]
    unsigned* Xsm = cs + 128 * 68;   // [130 px][68]
    int tid = threadIdx.x, lane = tid & 31, wid = tid >> 5;
    int n0 = blockIdx.x * 128;
    int m0 = blockIdx.y * 128;
    int y0 = n0 >> 8, x0 = n0 & 255;
    int r = lane >> 2, q = lane & 3;
    int wpix = (wid & 3) * 32, wch = (wid >> 2) * 64;

    int arow = (lane & 7) | (((lane >> 3) & 1) << 3);
    int acol = (lane >> 4) & 1;
    int brow = ((lane >> 4) & 1) * 8 + (lane & 7);
    int bcol = (lane >> 3) & 1;
    unsigned baseW = sm_addr(&Wsm[0]);
    unsigned baseX = sm_addr(&Xsm[0]);
    unsigned bAddr[4];
    #pragma unroll
    for (int p = 0; p < 4; p++)
        bAddr[p] = baseW + ((wch + p * 16 + brow) * 68 + bcol * 4) * 4u;

    float acc[2][8][4];
    #pragma unroll
    for (int i = 0; i < 2; i++)
        #pragma unroll
        for (int j = 0; j < 8; j++)
            #pragma unroll
            for (int v = 0; v < 4; v++) acc[i][j][v] = 0.f;

    for (int dy = 0; dy < 3; dy++) {
        int ys = y0 + dy - 1;
        bool yok = (ys >= 0) && (ys < IMGW);
        __syncthreads();
        for (int i = tid; i < 130 * 64; i += 256) {
            int px = i % 130, kp = i / 130;
            int xs = x0 - 1 + px;
            unsigned v = 0u;
            if (yok && xs >= 0 && xs < IMGW)
                v = Xp[(size_t)kp * HW + (ys << 8) + xs];
            Xsm[px * 68 + kp] = v;
        }
        for (int dx = 0; dx < 3; dx++) {
            int tap = dy * 3 + dx;
            __syncthreads();
            for (int i = tid; i < 128 * 16; i += 256) {
                int ch = i >> 4, k4 = (i & 15) << 2;
                *(uint4*)&Wsm[ch * 68 + k4] =
                    *(const uint4*)&Wp[(size_t)tap * (OUTC * 64) +
                                       (size_t)(m0 + ch) * 64 + k4];
            }
            __syncthreads();
            unsigned aA0 = baseX + ((wpix + dx + arow) * 68 + acol * 4) * 4u;
            unsigned aA1 = baseX + ((wpix + 16 + dx + arow) * 68 + acol * 4) * 4u;
            #pragma unroll
            for (int kk = 0; kk < 8; kk++) {
                unsigned a0[4], a1[4];
                LDSM4(a0, aA0 + kk * 32u);
                LDSM4(a1, aA1 + kk * 32u);
                #pragma unroll
                for (int p = 0; p < 4; p++) {
                    unsigned bb[4];
                    LDSM4(bb, bAddr[p] + kk * 32u);
                    MMA16(acc[0][2 * p], a0, bb[0], bb[1]);
                    MMA16(acc[1][2 * p], a1, bb[0], bb[1]);
                    MMA16(acc[0][2 * p + 1], a0, bb[2], bb[3]);
                    MMA16(acc[1][2 * p + 1], a1, bb[2], bb[3]);
                }
            }
        }
    }

    #pragma unroll
    for (int ti = 0; ti < 2; ti++) {
        int pix = n0 + wpix + ti * 16 + r;
        #pragma unroll
        for (int tj = 0; tj < 8; tj++) {
            int ch0 = m0 + wch + tj * 8 + 2 * q;
            int chp = ch0 >> 1;
            float b0v = bias[ch0], b1v = bias[ch0 + 1];
            float v0 = gelu_f(acc[ti][tj][0] + b0v);
            float v1 = gelu_f(acc[ti][tj][1] + b1v);
            float v2 = gelu_f(acc[ti][tj][2] + b0v);
            float v3 = gelu_f(acc[ti][tj][3] + b1v);
            Cp[(size_t)chp * HW + pix] = pk2(v0, v1);
            Cp[(size_t)chp * HW + pix + 8] = pk2(v2, v3);
        }
    }
}

// ---------------- host orchestration ----------------
extern "C" void kernel_launch(void* const* d_in, const int* in_sizes, int n_in,
                              void* d_out, int out_size) {
    const float* x     = (const float*)d_in[0];
    const float* ln1_g = (const float*)d_in[1];
    const float* ln1_b = (const float*)d_in[2];
    const float* wq    = (const float*)d_in[3];
    const float* wkv   = (const float*)d_in[4];
    const float* wo    = (const float*)d_in[5];
    const float* bo    = (const float*)d_in[6];
    const float* ln2_g = (const float*)d_in[7];
    const float* ln2_b = (const float*)d_in[8];
    const float* w_in  = (const float*)d_in[9];
    const float* b_in  = (const float*)d_in[10];
    const float* w_c3  = (const float*)d_in[11];
    const float* b_c3  = (const float*)d_in[12];
    const float* w_c1  = (const float*)d_in[13];
    const float* b_c1  = (const float*)d_in[14];
    const float* w_out = (const float*)d_in[15];
    const float* b_out = (const float*)d_in[16];
    float* out = (float*)d_out;

    float* px;
    unsigned *pqkv, *pxh, *pxl, *par;
    cudaGetSymbolAddress((void**)&px,   g_x);
    cudaGetSymbolAddress((void**)&pqkv, g_qkvp);
    cudaGetSymbolAddress((void**)&pxh,  g_xph);
    cudaGetSymbolAddress((void**)&pxl,  g_xpl);
    cudaGetSymbolAddress((void**)&par,  g_warena);

    cudaFuncSetAttribute(conv3_kernel,
                         cudaFuncAttributeMaxDynamicSharedMemorySize, 70176);
    cudaFuncSetAttribute(attn_kernel,
                         cudaFuncAttributeMaxDynamicSharedMemorySize, 72704);

    cudaMemcpyAsync(px, x, (size_t)DIMC * HW * sizeof(float),
                    cudaMemcpyDeviceToDevice);
    wconv_all<<<dim3(576, 13), 256>>>(wq, wkv, wo, w_in, w_c3, w_c1, w_out, par);

    for (int l = 0; l < 2; l++) {
        unsigned* wb = par + (size_t)l * LSTRIDE;
        ln_kernel<<<HW / 256, 256>>>(px, ln1_g + l * DIMC, ln1_b + l * DIMC, pxh);
        // merged q+kv GEMM: M = 1536
        gemm_bf16<<<dim3(512, 12), 256>>>(wb + OFF_Q, pxh, wb, pxh, wb, pxh, 1,
                                          nullptr, nullptr, nullptr, pqkv,
                                          3 * INNERC, DIMC);
        attn_kernel<<<2048, 256, 72704>>>(pqkv, pxh);
        gemm_bf16<<<dim3(512, 1), 256>>>(wb + OFF_WO, pxh, wb, pxh, wb, pxh, 1,
                                         bo + l * DIMC, px, px, nullptr,
                                         DIMC, INNERC);
        ln_kernel<<<HW / 256, 256>>>(px, ln2_g + l * DIMC, ln2_b + l * DIMC, pxh);
        gemm_bf16<<<dim3(512, 1), 256>>>(wb + OFF_WIN, pxh, wb, pxh, wb, pxh, 1,
                                         b_in + l * DIMC, nullptr, nullptr,
                                         pqkv, DIMC, DIMC);
        conv3_kernel<<<dim3(512, 2), 256, 70176>>>(wb + OFF_CONV, pqkv,
                                                   b_c3 + l * OUTC, pxh);
        gemm_bf16<<<dim3(512, 1), 256>>>(wb + OFF_WC1, pxh, wb, pxh, wb, pxh, 1,
                                         b_c1 + l * DIMC, px, px, nullptr,
                                         DIMC, OUTC);
    }
    xcvt<<<64 * HW / 256, 256>>>(px, pxh, pxl);
    gemm_bf16<<<dim3(512, 1), 256>>>(par + OFF_WOUT_H, pxh,
                                     par + OFF_WOUT_H, pxl,
                                     par + OFF_WOUT_L, pxh, 3,
                                     b_out, px, out, nullptr, DIMC, DIMC);
}

// round 13
// speedup vs baseline: 1.5925x; 1.2310x over previous
#include <cuda_runtime.h>
#include <cuda_bf16.h>
#include <math.h>

#define HW 65536
#define IMGW 256
#define DIMC 128
#define INNERC 512
#define OUTC 256
#define LEPS 1e-5f
#define ATT_SCALE 0.125f
#define LOG2E 1.4426950408889634f

// weight arena layout (u32 offsets)
#define OFF_Q     0
#define OFF_KV    32768
#define OFF_WO    98304
#define OFF_WIN   131072
#define OFF_WC1   139264
#define OFF_CONV  155648
#define LSTRIDE   303104
#define OFF_WOUT_H 606208
#define OFF_WOUT_L 614400
#define ARENA_SZ   622592

// ---------------- scratch (device globals; no allocation APIs) ----------------
__device__ float    g_x[DIMC * HW];
__device__ unsigned g_qkvp[768 * HW];
__device__ unsigned g_xph[256 * HW];
__device__ unsigned g_xpl[64 * HW];
__device__ unsigned g_warena[ARENA_SZ];

// ---------------- helpers ----------------
__device__ __forceinline__ unsigned pk2(float lo, float hi) {
    unsigned r;
    asm("cvt.rn.bf16x2.f32 %0, %1, %2;" : "=r"(r) : "f"(hi), "f"(lo));
    return r;
}
__device__ __forceinline__ float lof(float v) {
    return v - __bfloat162float(__float2bfloat16(v));
}
__device__ __forceinline__ float gelu_f(float v) {
    return 0.5f * v * (1.f + erff(v * 0.70710678118654752f));
}
__device__ __forceinline__ float ex2f(float v) {
    float r;
    asm("ex2.approx.f32 %0, %1;" : "=f"(r) : "f"(v));
    return r;
}
__device__ __forceinline__ unsigned prmtf(unsigned a, unsigned b, unsigned s) {
    unsigned r;
    asm("prmt.b32 %0,%1,%2,%3;" : "=r"(r) : "r"(a), "r"(b), "r"(s));
    return r;
}
__device__ __forceinline__ void cpa16(unsigned dst, const void* src) {
    asm volatile("cp.async.ca.shared.global [%0], [%1], 16;"
                 :: "r"(dst), "l"(src));
}
#define CP_COMMIT() asm volatile("cp.async.commit_group;")
#define CP_WAIT0()  asm volatile("cp.async.wait_group 0;")

#define MMA16(c, a, b0, b1)                                                    \
    asm volatile(                                                              \
        "mma.sync.aligned.m16n8k16.row.col.f32.bf16.bf16.f32 "                 \
        "{%0,%1,%2,%3},{%4,%5,%6,%7},{%8,%9},{%0,%1,%2,%3};"                   \
        : "+f"((c)[0]), "+f"((c)[1]), "+f"((c)[2]), "+f"((c)[3])               \
        : "r"((a)[0]), "r"((a)[1]), "r"((a)[2]), "r"((a)[3]), "r"(b0), "r"(b1))

#define LDSM4(R, addr)                                                         \
    asm volatile("ldmatrix.sync.aligned.m8n8.x4.shared.b16 {%0,%1,%2,%3}, [%4];" \
        : "=r"((R)[0]), "=r"((R)[1]), "=r"((R)[2]), "=r"((R)[3])               \
        : "r"(addr))

__device__ __forceinline__ unsigned sm_addr(const void* p) {
    return (unsigned)__cvta_generic_to_shared(p);
}

// ---------------- all weight conversions in one kernel ----------------
__global__ void wconv_all(const float* __restrict__ wq, const float* __restrict__ wkv,
                          const float* __restrict__ wo, const float* __restrict__ w_in,
                          const float* __restrict__ w_c3, const float* __restrict__ w_c1,
                          const float* __restrict__ w_out, unsigned* __restrict__ ar) {
    int i = blockIdx.x * 256 + threadIdx.x;
    int s = blockIdx.y;
    if (s < 12) {
        int l = s / 6, t = s % 6;
        unsigned* dst = ar + (size_t)l * LSTRIDE;
        if (t == 0) {
            if (i < 32768) {
                float2 f = *(const float2*)&wq[(size_t)l * 65536 + 2 * i];
                float sc = ATT_SCALE * LOG2E;
                dst[OFF_Q + i] = pk2(f.x * sc, f.y * sc);
            }
        } else if (t == 1) {
            if (i < 65536) {
                float2 f = *(const float2*)&wkv[(size_t)l * 131072 + 2 * i];
                dst[OFF_KV + i] = pk2(f.x, f.y);
            }
        } else if (t == 2) {
            if (i < 32768) {
                float2 f = *(const float2*)&wo[(size_t)l * 65536 + 2 * i];
                dst[OFF_WO + i] = pk2(f.x, f.y);
            }
        } else if (t == 3) {
            if (i < 8192) {
                float2 f = *(const float2*)&w_in[(size_t)l * 16384 + 2 * i];
                dst[OFF_WIN + i] = pk2(f.x, f.y);
            }
        } else if (t == 4) {
            if (i < 16384) {
                float2 f = *(const float2*)&w_c1[(size_t)l * 32768 + 2 * i];
                dst[OFF_WC1 + i] = pk2(f.x, f.y);
            }
        } else {
            if (i < 9 * OUTC * 64) {
                int tap = i / (OUTC * 64);
                int rem = i - tap * (OUTC * 64);
                int m = rem >> 6, kp = rem & 63;
                const float* w = w_c3 + (size_t)l * OUTC * DIMC * 9;
                float a = w[(size_t)m * (DIMC * 9) + (2 * kp) * 9 + tap];
                float b = w[(size_t)m * (DIMC * 9) + (2 * kp + 1) * 9 + tap];
                dst[OFF_CONV + i] = pk2(a, b);
            }
        }
    } else {
        if (i < 8192) {
            float2 f = *(const float2*)&w_out[2 * i];
            ar[OFF_WOUT_H + i] = pk2(f.x, f.y);
            ar[OFF_WOUT_L + i] = pk2(lof(f.x), lof(f.y));
        }
    }
}

__global__ void xcvt(const float* __restrict__ x, unsigned* __restrict__ yh,
                     unsigned* __restrict__ yl) {
    int i = blockIdx.x * 256 + threadIdx.x;
    int n = i & (HW - 1), kp = i >> 16;
    float v0 = x[(size_t)(2 * kp) * HW + n];
    float v1 = x[(size_t)(2 * kp + 1) * HW + n];
    yh[i] = pk2(v0, v1);
    yl[i] = pk2(lof(v0), lof(v1));
}

// ---------------- LayerNorm -> packed bf16 ----------------
__global__ void ln_kernel(const float* __restrict__ x, const float* __restrict__ g,
                          const float* __restrict__ b, unsigned* __restrict__ yh) {
    int p = blockIdx.x * blockDim.x + threadIdx.x;
    float s = 0.f, s2 = 0.f;
    #pragma unroll 8
    for (int c = 0; c < DIMC; c++) {
        float v = x[c * HW + p];
        s += v;
        s2 += v * v;
    }
    float mean = s * (1.f / DIMC);
    float var = fmaxf(s2 * (1.f / DIMC) - mean * mean, 0.f);
    float inv = 1.f / (sqrtf(var) + LEPS);
    #pragma unroll 4
    for (int cp = 0; cp < 64; cp++) {
        float v0 = (x[(2 * cp) * HW + p] - mean) * inv * g[2 * cp] + b[2 * cp];
        float v1 = (x[(2 * cp + 1) * HW + p] - mean) * inv * g[2 * cp + 1] + b[2 * cp + 1];
        yh[cp * HW + p] = pk2(v0, v1);
    }
}

// ---------------- bf16 GEMM: cp.async W staging + STS.128 X staging ----------
__global__ __launch_bounds__(256) void gemm_bf16(
    const unsigned* __restrict__ W0, const unsigned* __restrict__ X0,
    const unsigned* __restrict__ W1, const unsigned* __restrict__ X1,
    const unsigned* __restrict__ W2, const unsigned* __restrict__ X2,
    int npass, const float* __restrict__ bias, const float* __restrict__ res,
    float* __restrict__ C, unsigned* __restrict__ Cp, int M, int K)
{
    __shared__ unsigned Xs[2][128 * 12];
    __shared__ unsigned Ws[2][128 * 12];
    int tid = threadIdx.x, lane = tid & 31, wid = tid >> 5;
    int n0 = blockIdx.x * 128, m0 = blockIdx.y * 128;
    int KP = K >> 1;
    int sps = K / 16, nsteps = npass * sps;
    int r = lane >> 2, q = lane & 3;
    int wpix = (wid & 3) * 32, wch = (wid >> 2) * 64;
    int xn = tid & 127, xk = (tid >> 7) * 4;
    int wm = tid >> 1, wk = (tid & 1) * 4;

    int arow = (lane & 7) | (((lane >> 3) & 1) << 3);
    int acol = (lane >> 4) & 1;
    int brow = ((lane >> 4) & 1) * 8 + (lane & 7);
    int bcol = (lane >> 3) & 1;
    unsigned baseX = sm_addr(&Xs[0][0]);
    unsigned baseW = sm_addr(&Ws[0][0]);
    unsigned aAddr[2], bAddr[4];
    #pragma unroll
    for (int ti = 0; ti < 2; ti++)
        aAddr[ti] = baseX + ((wpix + ti * 16 + arow) * 12 + acol * 4) * 4u;
    #pragma unroll
    for (int p = 0; p < 4; p++)
        bAddr[p] = baseW + ((wch + p * 16 + brow) * 12 + bcol * 4) * 4u;
    const unsigned BUF = 128 * 12 * 4;
    unsigned wdst = baseW + (wm * 12 + wk) * 4u;
    unsigned xdst = baseX + (xn * 12 + xk) * 4u;

    const unsigned* Wsel[3] = {W0, W1, W2};
    const unsigned* Xsel[3] = {X0, X1, X2};
    size_t wrow = (size_t)(m0 + wm) * KP + wk;
    size_t xoff = (size_t)(n0 + xn);

    float acc[2][8][4];
    #pragma unroll
    for (int i = 0; i < 2; i++)
        #pragma unroll
        for (int j = 0; j < 8; j++)
            #pragma unroll
            for (int v = 0; v < 4; v++) acc[i][j][v] = 0.f;

    unsigned xr[4];
    // prologue: W via cp.async, X via LDG + STS.128
    cpa16(wdst, W0 + wrow);
    CP_COMMIT();
    #pragma unroll
    for (int j = 0; j < 4; j++) xr[j] = X0[(size_t)(xk + j) * HW + xoff];
    *(uint4*)&Xs[0][xn * 12 + xk] = make_uint4(xr[0], xr[1], xr[2], xr[3]);
    CP_WAIT0();
    __syncthreads();

    for (int s = 0; s < nsteps; s++) {
        int cur = s & 1;
        unsigned co = cur ? BUF : 0u;
        if (s + 1 < nsteps) {
            int s1 = s + 1;
            int seg = s1 / sps;
            int kp0 = (s1 - seg * sps) * 8;
            int nb = cur ^ 1;
            cpa16(wdst + (nb ? BUF : 0u), Wsel[seg] + wrow + kp0);
            CP_COMMIT();
            const unsigned* Xg = Xsel[seg];
            #pragma unroll
            for (int j = 0; j < 4; j++)
                xr[j] = Xg[(size_t)(kp0 + xk + j) * HW + xoff];
        }
        unsigned a0[4], a1[4];
        LDSM4(a0, aAddr[0] + co);
        LDSM4(a1, aAddr[1] + co);
        #pragma unroll
        for (int p = 0; p < 4; p++) {
            unsigned bb[4];
            LDSM4(bb, bAddr[p] + co);
            MMA16(acc[0][2 * p], a0, bb[0], bb[1]);
            MMA16(acc[1][2 * p], a1, bb[0], bb[1]);
            MMA16(acc[0][2 * p + 1], a0, bb[2], bb[3]);
            MMA16(acc[1][2 * p + 1], a1, bb[2], bb[3]);
        }
        if (s + 1 < nsteps) {
            int nb = cur ^ 1;
            *(uint4*)&Xs[nb][xn * 12 + xk] = make_uint4(xr[0], xr[1], xr[2], xr[3]);
            CP_WAIT0();
            __syncthreads();
        }
    }

    #pragma unroll
    for (int ti = 0; ti < 2; ti++) {
        int pix = n0 + wpix + ti * 16 + r;
        #pragma unroll
        for (int tj = 0; tj < 8; tj++) {
            int ch0 = m0 + wch + tj * 8 + 2 * q;
            float b0v = bias ? bias[ch0] : 0.f;
            float b1v = bias ? bias[ch0 + 1] : 0.f;
            float v0 = acc[ti][tj][0] + b0v, v1 = acc[ti][tj][1] + b1v;
            float v2 = acc[ti][tj][2] + b0v, v3 = acc[ti][tj][3] + b1v;
            if (Cp) {
                int chp = ch0 >> 1;
                Cp[(size_t)chp * HW + pix] = pk2(v0, v1);
                Cp[(size_t)chp * HW + pix + 8] = pk2(v2, v3);
            } else {
                size_t i00 = (size_t)ch0 * HW + pix;
                size_t i10 = (size_t)(ch0 + 1) * HW + pix;
                if (res) {
                    v0 += res[i00]; v1 += res[i10];
                    v2 += res[i00 + 8]; v3 += res[i10 + 8];
                }
                C[i00] = v0; C[i10] = v1;
                C[i00 + 8] = v2; C[i10 + 8] = v3;
            }
        }
    }
}

// ---------------- window attention: fully-resident K/V, barrier-free mainloop --
// smem (dynamic 107520B): Qs [256][36] | Ks [256][36] | Vs [64][132]; Os overlays Qs.
__global__ __launch_bounds__(256, 2) void attn_kernel(const unsigned* __restrict__ qkv,
                                                      unsigned* __restrict__ outp) {
    extern __shared__ unsigned su[];
    unsigned* Qs = su;                 // 9216 u32
    unsigned* Ks = su + 9216;          // 9216 u32
    unsigned* Vs = su + 18432;         // 8448 u32
    unsigned* Os = su;
    int blk = blockIdx.x;
    int wx = blk & 15, wy = (blk >> 4) & 15, h = blk >> 8;
    int tid = threadIdx.x, lane = tid & 31, wid = tid >> 5;
    int wbase = (wy << 12) | (wx << 4);
    int r = lane >> 2, q = lane & 3;
    const unsigned* Qg = qkv + (size_t)(h * 32) * HW;
    const unsigned* Kg = qkv + (size_t)(256 + h * 32) * HW;
    const unsigned* Vg = qkv + (size_t)(512 + h * 32) * HW;

    int arow = (lane & 7) | (((lane >> 3) & 1) << 3);
    int acol = (lane >> 4) & 1;
    int brow = ((lane >> 4) & 1) * 8 + (lane & 7);
    int bcol = (lane >> 3) & 1;
    unsigned baseS = sm_addr(&su[0]);
    int wm = wid * 32;

    // stage Q, K, V (all resident; loads overlap with high MLP)
    for (int i = tid; i < 256 * 32; i += 256) {
        int n = i & 255, dp = i >> 8;
        int p = wbase + ((n >> 4) << 8) + (n & 15);
        Qs[n * 36 + dp] = Qg[(size_t)dp * HW + p];
        Ks[n * 36 + dp] = Kg[(size_t)dp * HW + p];
    }
    for (int i = tid; i < 32 * 128; i += 256) {
        int dp = i >> 7, jp = i & 127;
        int j0 = 2 * jp;
        int pj = wbase + ((j0 >> 4) << 8) + (j0 & 15);
        uint2 vv = *(const uint2*)&Vg[(size_t)dp * HW + pj];
        Vs[(2 * dp) * 132 + jp] = prmtf(vv.x, vv.y, 0x5410u);
        Vs[(2 * dp + 1) * 132 + jp] = prmtf(vv.x, vv.y, 0x7632u);
    }
    __syncthreads();

    // preload Q fragments
    unsigned aQ[2][4][4];
    #pragma unroll
    for (int ti = 0; ti < 2; ti++) {
        unsigned ab = baseS + ((wm + ti * 16 + arow) * 36 + acol * 4) * 4u;
        #pragma unroll
        for (int kk = 0; kk < 4; kk++)
            LDSM4(aQ[ti][kk], ab + kk * 32u);
    }

    unsigned kb = baseS + 9216u * 4u + ((unsigned)(brow * 36 + bcol * 4)) * 4u;
    unsigned vAddr[4];
    #pragma unroll
    for (int p = 0; p < 4; p++)
        vAddr[p] = baseS + 18432u * 4u +
                   ((unsigned)((p * 16 + brow) * 132 + bcol * 4)) * 4u;

    float o[2][8][4];
    #pragma unroll
    for (int i = 0; i < 2; i++)
        #pragma unroll
        for (int j = 0; j < 8; j++)
            #pragma unroll
            for (int v = 0; v < 4; v++) o[i][j][v] = 0.f;
    float rs[2][2] = {{0.f, 0.f}, {0.f, 0.f}};

    // barrier-free mainloop over all 16 column blocks
    #pragma unroll 4
    for (int tjp = 0; tjp < 16; tjp++) {
        float c[2][2][4];
        #pragma unroll
        for (int ti = 0; ti < 2; ti++)
            #pragma unroll
            for (int hh = 0; hh < 2; hh++)
                #pragma unroll
                for (int v = 0; v < 4; v++) c[ti][hh][v] = 0.f;
        #pragma unroll
        for (int kk = 0; kk < 4; kk++) {
            unsigned bb[4];
            LDSM4(bb, kb + tjp * 2304u + kk * 32u);
            MMA16(c[0][0], aQ[0][kk], bb[0], bb[1]);
            MMA16(c[0][1], aQ[0][kk], bb[2], bb[3]);
            MMA16(c[1][0], aQ[1][kk], bb[0], bb[1]);
            MMA16(c[1][1], aQ[1][kk], bb[2], bb[3]);
        }
        unsigned aP[2][4];
        #pragma unroll
        for (int ti = 0; ti < 2; ti++) {
            float e00 = ex2f(c[ti][0][0]), e01 = ex2f(c[ti][0][1]);
            float e02 = ex2f(c[ti][0][2]), e03 = ex2f(c[ti][0][3]);
            float e10 = ex2f(c[ti][1][0]), e11 = ex2f(c[ti][1][1]);
            float e12 = ex2f(c[ti][1][2]), e13 = ex2f(c[ti][1][3]);
            rs[ti][0] += e00 + e01 + e10 + e11;
            rs[ti][1] += e02 + e03 + e12 + e13;
            aP[ti][0] = pk2(e00, e01);
            aP[ti][1] = pk2(e02, e03);
            aP[ti][2] = pk2(e10, e11);
            aP[ti][3] = pk2(e12, e13);
        }
        #pragma unroll
        for (int tdjp = 0; tdjp < 4; tdjp++) {
            unsigned bv[4];
            LDSM4(bv, vAddr[tdjp] + tjp * 32u);
            MMA16(o[0][2 * tdjp], aP[0], bv[0], bv[1]);
            MMA16(o[0][2 * tdjp + 1], aP[0], bv[2], bv[3]);
            MMA16(o[1][2 * tdjp], aP[1], bv[0], bv[1]);
            MMA16(o[1][2 * tdjp + 1], aP[1], bv[2], bv[3]);
        }
    }

    #pragma unroll
    for (int ti = 0; ti < 2; ti++) {
        #pragma unroll
        for (int hh = 0; hh < 2; hh++) {
            rs[ti][hh] += __shfl_xor_sync(0xffffffffu, rs[ti][hh], 1);
            rs[ti][hh] += __shfl_xor_sync(0xffffffffu, rs[ti][hh], 2);
        }
    }

    __syncthreads();   // everyone done with Qs (frag preload) before Os overlay
    #pragma unroll
    for (int ti = 0; ti < 2; ti++) {
        int t0 = wm + ti * 16 + r;
        float i0 = 1.f / rs[ti][0], i1 = 1.f / rs[ti][1];
        #pragma unroll
        for (int tdj = 0; tdj < 8; tdj++) {
            int kpl = tdj * 4 + q;
            Os[kpl * 260 + t0] = pk2(o[ti][tdj][0] * i0, o[ti][tdj][1] * i0);
            Os[kpl * 260 + t0 + 8] = pk2(o[ti][tdj][2] * i1, o[ti][tdj][3] * i1);
        }
    }
    __syncthreads();
    for (int i = tid; i < 32 * 256; i += 256) {
        int kpl = i >> 8, n = i & 255;
        int p = wbase + ((n >> 4) << 8) + (n & 15);
        outp[(size_t)(h * 32 + kpl) * HW + p] = Os[kpl * 260 + n];
    }
}

// ---------------- 3x3 conv implicit GEMM + bias + GELU ----------------
__global__ __launch_bounds__(256, 2) void conv3_kernel(
    const unsigned* __restrict__ Wp, const unsigned* __restrict__ Xp,
    const float* __restrict__ bias, unsigned* __restrict__ Cp)
{
    extern __shared__ unsigned cs[];
    unsigned* Wsm = cs;              // [128 ch][68]
    unsigned* Xsm = cs + 128 * 68;   // [130 px][68]
    int tid = threadIdx.x, lane = tid & 31, wid = tid >> 5;
    int n0 = blockIdx.x * 128;
    int m0 = blockIdx.y * 128;
    int y0 = n0 >> 8, x0 = n0 & 255;
    int r = lane >> 2, q = lane & 3;
    int wpix = (wid & 3) * 32, wch = (wid >> 2) * 64;

    int arow = (lane & 7) | (((lane >> 3) & 1) << 3);
    int acol = (lane >> 4) & 1;
    int brow = ((lane >> 4) & 1) * 8 + (lane & 7);
    int bcol = (lane >> 3) & 1;
    unsigned baseW = sm_addr(&Wsm[0]);
    unsigned baseX = sm_addr(&Xsm[0]);
    unsigned bAddr[4];
    #pragma unroll
    for (int p = 0; p < 4; p++)
        bAddr[p] = baseW + ((wch + p * 16 + brow) * 68 + bcol * 4) * 4u;

    float acc[2][8][4];
    #pragma unroll
    for (int i = 0; i < 2; i++)
        #pragma unroll
        for (int j = 0; j < 8; j++)
            #pragma unroll
            for (int v = 0; v < 4; v++) acc[i][j][v] = 0.f;

    for (int dy = 0; dy < 3; dy++) {
        int ys = y0 + dy - 1;
        bool yok = (ys >= 0) && (ys < IMGW);
        __syncthreads();
        for (int i = tid; i < 130 * 64; i += 256) {
            int px = i % 130, kp = i / 130;
            int xs = x0 - 1 + px;
            unsigned v = 0u;
            if (yok && xs >= 0 && xs < IMGW)
                v = Xp[(size_t)kp * HW + (ys << 8) + xs];
            Xsm[px * 68 + kp] = v;
        }
        for (int dx = 0; dx < 3; dx++) {
            int tap = dy * 3 + dx;
            __syncthreads();
            for (int i = tid; i < 128 * 16; i += 256) {
                int ch = i >> 4, k4 = (i & 15) << 2;
                *(uint4*)&Wsm[ch * 68 + k4] =
                    *(const uint4*)&Wp[(size_t)tap * (OUTC * 64) +
                                       (size_t)(m0 + ch) * 64 + k4];
            }
            __syncthreads();
            unsigned aA0 = baseX + ((wpix + dx + arow) * 68 + acol * 4) * 4u;
            unsigned aA1 = baseX + ((wpix + 16 + dx + arow) * 68 + acol * 4) * 4u;
            #pragma unroll
            for (int kk = 0; kk < 8; kk++) {
                unsigned a0[4], a1[4];
                LDSM4(a0, aA0 + kk * 32u);
                LDSM4(a1, aA1 + kk * 32u);
                #pragma unroll
                for (int p = 0; p < 4; p++) {
                    unsigned bb[4];
                    LDSM4(bb, bAddr[p] + kk * 32u);
                    MMA16(acc[0][2 * p], a0, bb[0], bb[1]);
                    MMA16(acc[1][2 * p], a1, bb[0], bb[1]);
                    MMA16(acc[0][2 * p + 1], a0, bb[2], bb[3]);
                    MMA16(acc[1][2 * p + 1], a1, bb[2], bb[3]);
                }
            }
        }
    }

    #pragma unroll
    for (int ti = 0; ti < 2; ti++) {
        int pix = n0 + wpix + ti * 16 + r;
        #pragma unroll
        for (int tj = 0; tj < 8; tj++) {
            int ch0 = m0 + wch + tj * 8 + 2 * q;
            int chp = ch0 >> 1;
            float b0v = bias[ch0], b1v = bias[ch0 + 1];
            float v0 = gelu_f(acc[ti][tj][0] + b0v);
            float v1 = gelu_f(acc[ti][tj][1] + b1v);
            float v2 = gelu_f(acc[ti][tj][2] + b0v);
            float v3 = gelu_f(acc[ti][tj][3] + b1v);
            Cp[(size_t)chp * HW + pix] = pk2(v0, v1);
            Cp[(size_t)chp * HW + pix + 8] = pk2(v2, v3);
        }
    }
}

// ---------------- host orchestration ----------------
extern "C" void kernel_launch(void* const* d_in, const int* in_sizes, int n_in,
                              void* d_out, int out_size) {
    const float* x     = (const float*)d_in[0];
    const float* ln1_g = (const float*)d_in[1];
    const float* ln1_b = (const float*)d_in[2];
    const float* wq    = (const float*)d_in[3];
    const float* wkv   = (const float*)d_in[4];
    const float* wo    = (const float*)d_in[5];
    const float* bo    = (const float*)d_in[6];
    const float* ln2_g = (const float*)d_in[7];
    const float* ln2_b = (const float*)d_in[8];
    const float* w_in  = (const float*)d_in[9];
    const float* b_in  = (const float*)d_in[10];
    const float* w_c3  = (const float*)d_in[11];
    const float* b_c3  = (const float*)d_in[12];
    const float* w_c1  = (const float*)d_in[13];
    const float* b_c1  = (const float*)d_in[14];
    const float* w_out = (const float*)d_in[15];
    const float* b_out = (const float*)d_in[16];
    float* out = (float*)d_out;

    float* px;
    unsigned *pqkv, *pxh, *pxl, *par;
    cudaGetSymbolAddress((void**)&px,   g_x);
    cudaGetSymbolAddress((void**)&pqkv, g_qkvp);
    cudaGetSymbolAddress((void**)&pxh,  g_xph);
    cudaGetSymbolAddress((void**)&pxl,  g_xpl);
    cudaGetSymbolAddress((void**)&par,  g_warena);

    cudaFuncSetAttribute(conv3_kernel,
                         cudaFuncAttributeMaxDynamicSharedMemorySize, 70176);
    cudaFuncSetAttribute(attn_kernel,
                         cudaFuncAttributeMaxDynamicSharedMemorySize, 107520);

    cudaMemcpyAsync(px, x, (size_t)DIMC * HW * sizeof(float),
                    cudaMemcpyDeviceToDevice);
    wconv_all<<<dim3(576, 13), 256>>>(wq, wkv, wo, w_in, w_c3, w_c1, w_out, par);

    for (int l = 0; l < 2; l++) {
        unsigned* wb = par + (size_t)l * LSTRIDE;
        ln_kernel<<<HW / 256, 256>>>(px, ln1_g + l * DIMC, ln1_b + l * DIMC, pxh);
        gemm_bf16<<<dim3(512, 12), 256>>>(wb + OFF_Q, pxh, wb, pxh, wb, pxh, 1,
                                          nullptr, nullptr, nullptr, pqkv,
                                          3 * INNERC, DIMC);
        attn_kernel<<<2048, 256, 107520>>>(pqkv, pxh);
        gemm_bf16<<<dim3(512, 1), 256>>>(wb + OFF_WO, pxh, wb, pxh, wb, pxh, 1,
                                         bo + l * DIMC, px, px, nullptr,
                                         DIMC, INNERC);
        ln_kernel<<<HW / 256, 256>>>(px, ln2_g + l * DIMC, ln2_b + l * DIMC, pxh);
        gemm_bf16<<<dim3(512, 1), 256>>>(wb + OFF_WIN, pxh, wb, pxh, wb, pxh, 1,
                                         b_in + l * DIMC, nullptr, nullptr,
                                         pqkv, DIMC, DIMC);
        conv3_kernel<<<dim3(512, 2), 256, 70176>>>(wb + OFF_CONV, pqkv,
                                                   b_c3 + l * OUTC, pxh);
        gemm_bf16<<<dim3(512, 1), 256>>>(wb + OFF_WC1, pxh, wb, pxh, wb, pxh, 1,
                                         b_c1 + l * DIMC, px, px, nullptr,
                                         DIMC, OUTC);
    }
    xcvt<<<64 * HW / 256, 256>>>(px, pxh, pxl);
    gemm_bf16<<<dim3(512, 1), 256>>>(par + OFF_WOUT_H, pxh,
                                     par + OFF_WOUT_H, pxl,
                                     par + OFF_WOUT_L, pxh, 3,
                                     b_out, px, out, nullptr, DIMC, DIMC);
}